// round 14
// baseline (speedup 1.0000x reference)
#include <cuda_runtime.h>
#include <cuda_bf16.h>
#include <cstdint>

// Problem constants
#define BB 64
#define LL 512
#define TT 8
#define DD 1024
#define CC 3
#define NHOP 6
#define NPROJ 24          // [w_a, u_0..u_4, z_{c,k} c=0..2 k=0..5]
#define CHAIN_CTAS 256
#define HEAVY_CTAS 148
#define NBLK ((BB * LL) / 32)   // 1024 row-blocks of 32

// Scratch (device globals — no allocation allowed)
__device__ float g_U[7 * DD * 4];      // levels 0..6 of [w_b, wout0..2], layout [(lvl*D+d)*4+c]
__device__ float g_Proj[NPROJ * DD];   // packed projection matrix [p][d]
__device__ float g_P[(size_t)BB * LL * NPROJ];  // per-row projected dots (incl. v_loc)

// software grid barrier state (gen monotonic across graph replays)
__device__ unsigned g_cnt = 0;
__device__ unsigned g_gen = 0;

// packed f32x2 FMA (FFMA2) — only reachable via PTX
__device__ __forceinline__ unsigned long long fma2(unsigned long long a,
                                                   unsigned long long b,
                                                   unsigned long long c) {
    unsigned long long d;
    asm("fma.rn.f32x2 %0, %1, %2, %3;" : "=l"(d) : "l"(a), "l"(b), "l"(c));
    return d;
}

__device__ __forceinline__ uint32_t smem_u32(const void* p) {
    uint32_t a;
    asm("{ .reg .u64 t; cvta.to.shared.u64 t, %1; cvt.u32.u64 %0, t; }" : "=r"(a) : "l"(p));
    return a;
}
__device__ __forceinline__ void cp_async16(uint32_t dst, const void* src) {
    asm volatile("cp.async.cg.shared.global [%0], [%1], 16;" :: "r"(dst), "l"(src));
}
#define CP_COMMIT() asm volatile("cp.async.commit_group;")
#define CP_WAIT2()  asm volatile("cp.async.wait_group 2;")

__device__ __forceinline__ void grid_sync() {
    __threadfence();
    __syncthreads();
    if (threadIdx.x == 0) {
        unsigned gen = *(volatile unsigned*)&g_gen;   // read BEFORE arriving
        unsigned t = atomicAdd(&g_cnt, 1);
        if (t == CHAIN_CTAS - 1) {
            g_cnt = 0;
            __threadfence();
            atomicAdd(&g_gen, 1);
        } else {
            while (*(volatile unsigned*)&g_gen == gen) { __nanosleep(64); }
        }
    }
    __syncthreads();
}

// ---------------------------------------------------------------------------
// K1 (fused chain): init level-0, 6x (level k+1 = W_lin @ level k, 4 cols),
// then pack the 24 projection vectors. ONE launch, 256 all-resident CTAs
// (2/SM). Each CTA owns 4 rows, 2 warps per row (MLP 4 per lane).
// ---------------------------------------------------------------------------
__global__ void __launch_bounds__(256) k_chain_all(
    const float* __restrict__ W, const float* __restrict__ w_attn,
    const float* __restrict__ W_out)
{
    __shared__ float sx0[DD], sx1[DD], sx2[DD], sx3[DD];
    __shared__ float spart[8][4];
    int tid = threadIdx.x, bid = blockIdx.x;
    int lane = tid & 31, warp = tid >> 5;
    int gt = bid * 256 + tid;

    // init level 0: col0 = w_b, col 1+c = W_out[:,c]
    for (int d = gt; d < DD; d += CHAIN_CTAS * 256) {
        g_U[d * 4 + 0] = w_attn[DD + d];
        g_U[d * 4 + 1] = W_out[d * CC + 0];
        g_U[d * 4 + 2] = W_out[d * CC + 1];
        g_U[d * 4 + 3] = W_out[d * CC + 2];
    }
    grid_sync();

    int row = bid * 4 + (warp >> 1);      // 256 CTAs * 4 rows = 1024
    int half = warp & 1;
    const float4* Wv = (const float4*)(W + (size_t)row * DD);

    for (int k = 0; k < NHOP; k++) {
        // load X level k into smem SoA (L2-only loads: avoid stale L1)
        const float4* Xv = (const float4*)(g_U + (size_t)k * DD * 4);
        for (int i = tid; i < DD; i += 256) {
            float4 v = __ldcg(Xv + i);
            sx0[i] = v.x; sx1[i] = v.y; sx2[i] = v.z; sx3[i] = v.w;
        }
        __syncthreads();

        float a0 = 0.f, a1 = 0.f, a2 = 0.f, a3 = 0.f;
        #pragma unroll
        for (int pass = 0; pass < 4; pass++) {
            int idx = half * 128 + pass * 32 + lane;   // float4 index into row
            float4 w = Wv[idx];
            float4 x0 = *(const float4*)&sx0[idx * 4];
            float4 x1 = *(const float4*)&sx1[idx * 4];
            float4 x2 = *(const float4*)&sx2[idx * 4];
            float4 x3 = *(const float4*)&sx3[idx * 4];
            a0 += w.x * x0.x + w.y * x0.y + w.z * x0.z + w.w * x0.w;
            a1 += w.x * x1.x + w.y * x1.y + w.z * x1.z + w.w * x1.w;
            a2 += w.x * x2.x + w.y * x2.y + w.z * x2.z + w.w * x2.w;
            a3 += w.x * x3.x + w.y * x3.y + w.z * x3.z + w.w * x3.w;
        }
        #pragma unroll
        for (int off = 16; off; off >>= 1) {
            a0 += __shfl_xor_sync(0xffffffffu, a0, off);
            a1 += __shfl_xor_sync(0xffffffffu, a1, off);
            a2 += __shfl_xor_sync(0xffffffffu, a2, off);
            a3 += __shfl_xor_sync(0xffffffffu, a3, off);
        }
        if (lane == 0) {
            spart[warp][0] = a0; spart[warp][1] = a1;
            spart[warp][2] = a2; spart[warp][3] = a3;
        }
        __syncthreads();
        if (tid < 16) {
            int rl = tid >> 2, col = tid & 3;
            float v = spart[rl * 2 + 0][col] + spart[rl * 2 + 1][col];
            g_U[((size_t)(k + 1) * DD + bid * 4 + rl) * 4 + col] = v;
        }
        grid_sync();    // level k+1 complete & visible
    }

    // pack projections: p=0 -> w_a; p=1..5 -> u_{p-1}; p=6+c*6+kk -> z_{c,kk}
    for (int i = gt; i < NPROJ * DD; i += CHAIN_CTAS * 256) {
        int p = i >> 10, d = i & (DD - 1);
        float v;
        if (p == 0)      v = w_attn[d];
        else if (p < 6)  v = __ldcg(&g_U[((size_t)(p - 1) * DD + d) * 4 + 0]);
        else {
            int c = (p - 6) / 6, kk = (p - 6) % 6;
            v = __ldcg(&g_U[((size_t)kk * DD + d) * 4 + 1 + c]);
        }
        g_Proj[i] = v;
    }
}

// ---------------------------------------------------------------------------
// K3 (heavy): P[row][p] = v_loc(row) * dot(E[ctx[row]], Proj[p]), 24 projs.
// Persistent grid=148.  Proj (96 KB) in smem once per CTA.  E staged through
// a 4-slot / depth-3 cp.async pipeline (ONE barrier per chunk; the barrier at
// iter ch proves slot (ch+3)&3 was fully consumed at iter ch-1, so the
// copy-after-compute into it is race-free).  Thread tile: 8 rows x 6 projs,
// packed FFMA2.  dl = tid&15, pg = (tid>>4)&3, rg = tid>>6.
// ---------------------------------------------------------------------------
#define E_SLOT_ROW 68          // 64 + 4 pad floats
__global__ void __launch_bounds__(256, 1) k_heavy(
    const int* __restrict__ ctx_ids, const float* __restrict__ E,
    const int* __restrict__ ctx_len, const int* __restrict__ tgt_off)
{
    extern __shared__ float smem[];
    float* sproj = smem;                                  // [24][1024] = 96 KB
    float* sE    = smem + NPROJ * DD;                     // [4][32][E_SLOT_ROW]

    int tid = threadIdx.x;

    {   // one-time Proj load
        const float4* src = (const float4*)g_Proj;
        float4* dst = (float4*)sproj;
        for (int i = tid; i < NPROJ * DD / 4; i += 256) dst[i] = src[i];
    }

    int dl = tid & 15;
    int pg = (tid >> 4) & 3;
    int rg = tid >> 6;
    const float* pbase = sproj + (size_t)(pg * 6) * DD + dl * 4;

    // staging map: thread stages E-tile float4 #tid and #tid+256 (512 total)
    int r0 = tid >> 4,         c0 = tid & 15;
    int r1 = (tid + 256) >> 4, c1 = tid & 15;
    uint32_t sE0 = smem_u32(&sE[0]) + (uint32_t)(r0 * E_SLOT_ROW + c0 * 4) * 4u;
    uint32_t sE1 = smem_u32(&sE[0]) + (uint32_t)(r1 * E_SLOT_ROW + c1 * 4) * 4u;
    const uint32_t slotBytes = 32 * E_SLOT_ROW * 4;

    __syncthreads();

    for (int blk = blockIdx.x; blk < NBLK; blk += HEAVY_CTAS) {
        int row0 = blk * 32;

        const float* eb0 = E + (size_t)__ldg(&ctx_ids[row0 + r0]) * DD + c0 * 4;
        const float* eb1 = E + (size_t)__ldg(&ctx_ids[row0 + r1]) * DD + c1 * 4;

        __syncthreads();   // previous blk's reads done before refilling slots

        // prologue: chunks 0,1,2 into slots 0,1,2
        #pragma unroll
        for (int c = 0; c < 3; c++) {
            cp_async16(sE0 + c * slotBytes, eb0 + c * 64);
            cp_async16(sE1 + c * slotBytes, eb1 + c * 64);
            CP_COMMIT();
        }

        unsigned long long acc[8][6];
        #pragma unroll
        for (int r = 0; r < 8; r++)
            #pragma unroll
            for (int p = 0; p < 6; p++) acc[r][p] = 0ull;

        for (int ch = 0; ch < 16; ch++) {
            CP_WAIT2();
            __syncthreads();

            int slot = ch & 3;
            const float* se = sE + (size_t)slot * 32 * E_SLOT_ROW;

            ulonglong2 pv[6];
            #pragma unroll
            for (int p = 0; p < 6; p++)
                pv[p] = *(const ulonglong2*)(pbase + (size_t)p * DD + ch * 64);

            #pragma unroll
            for (int r = 0; r < 8; r++) {
                ulonglong2 e2 = *(const ulonglong2*)
                    (se + (size_t)(rg * 8 + r) * E_SLOT_ROW + dl * 4);
                #pragma unroll
                for (int p = 0; p < 6; p++) {
                    unsigned long long a = acc[r][p];
                    a = fma2(e2.x, pv[p].x, a);
                    a = fma2(e2.y, pv[p].y, a);
                    acc[r][p] = a;
                }
            }

            if (ch + 3 < 16) {   // copy chunk ch+3 into slot (ch+3)&3
                int ns = (ch + 3) & 3;
                cp_async16(sE0 + ns * slotBytes, eb0 + (ch + 3) * 64);
                cp_async16(sE1 + ns * slotBytes, eb1 + (ch + 3) * 64);
            }
            CP_COMMIT();         // always commit (empty groups keep counts uniform)
        }

        // collapse packed halves, then reduce over the 16 d-lanes
        float s[8][6];
        #pragma unroll
        for (int r = 0; r < 8; r++)
            #pragma unroll
            for (int p = 0; p < 6; p++) {
                float2 f = *(float2*)&acc[r][p];
                s[r][p] = f.x + f.y;
            }
        #pragma unroll
        for (int off = 8; off; off >>= 1)
            #pragma unroll
            for (int r = 0; r < 8; r++)
                #pragma unroll
                for (int p = 0; p < 6; p++)
                    s[r][p] += __shfl_xor_sync(0xffffffffu, s[r][p], off);

        if (dl == 0) {
            int b = row0 >> 9;
            int len = __ldg(&ctx_len[b]);
            int toff = __ldg(&tgt_off[b]);
            #pragma unroll
            for (int r = 0; r < 8; r++) {
                int row = row0 + rg * 8 + r;
                int l = row & (LL - 1);
                float v = 0.f;
                if (l < len) v = 1.f - fabsf((float)(l - toff)) / (float)len;
                float2* dst = (float2*)(g_P + (size_t)row * NPROJ + pg * 6);
                dst[0] = make_float2(s[r][0] * v, s[r][1] * v);
                dst[1] = make_float2(s[r][2] * v, s[r][3] * v);
                dst[2] = make_float2(s[r][4] * v, s[r][5] * v);
            }
        }
    }
}

// ---------------------------------------------------------------------------
// K4 (solve): one CTA per batch. v_aspect projections, b_lin projections,
// 6-hop scalar recursion (softmax over L=512, 23 weighted sums per hop),
// emit 3 logits.
// ---------------------------------------------------------------------------
__global__ void __launch_bounds__(256) k_solve(
    const int* __restrict__ tgt_ids, const int* __restrict__ ctx_len,
    const int* __restrict__ tgt_len, const float* __restrict__ E,
    const float* __restrict__ b_attn, const float* __restrict__ b_lin,
    const float* __restrict__ b_out, float* __restrict__ out)
{
    int b = blockIdx.x, tid = threadIdx.x;
    int lane = tid & 31, warp = tid >> 5;

    __shared__ float semean[DD];
    __shared__ float sw[8][33];
    __shared__ float sq[6][23];
    __shared__ float sbd[24];
    __shared__ float sc0[9];
    __shared__ float sbcast[2];

    int len  = ctx_len[b];
    int tlen = tgt_len[b];

    for (int d = tid; d < DD; d += 256) {
        float s = 0.f;
        for (int t = 0; t < tlen; t++)
            s += E[(size_t)tgt_ids[b * TT + t] * DD + d];
        semean[d] = s / (float)tlen;
    }
    __syncthreads();

    float part[32];
    #pragma unroll
    for (int i = 0; i < 32; i++) part[i] = 0.f;
    for (int d = tid; d < DD; d += 256) {
        float em = semean[d];
        float bl = b_lin[d];
        #pragma unroll
        for (int h = 0; h < 6; h++) part[h] += em * g_U[((size_t)h * DD + d) * 4 + 0];
        #pragma unroll
        for (int c = 0; c < 3; c++) part[6 + c] += em * g_U[((size_t)6 * DD + d) * 4 + 1 + c];
        #pragma unroll
        for (int p = 1; p < 24; p++) part[8 + p] += bl * g_Proj[(size_t)p * DD + d];
    }
    #pragma unroll
    for (int off = 16; off; off >>= 1)
        #pragma unroll
        for (int i = 0; i < 32; i++)
            part[i] += __shfl_xor_sync(0xffffffffu, part[i], off);
    if (lane == 0) {
        #pragma unroll
        for (int i = 0; i < 32; i++) sw[warp][i] = part[i];
    }
    __syncthreads();
    if (tid < 32) {
        float s = 0.f;
        #pragma unroll
        for (int w = 0; w < 8; w++) s += sw[w][tid];
        if (tid < 9) sc0[tid] = s;
        else         sbd[tid - 8] = s;
    }
    __syncthreads();

    int l0 = tid, l1 = tid + 256;
    float P0[24], P1[24];
    {
        const float4* p0 = (const float4*)(g_P + ((size_t)b * LL + l0) * NPROJ);
        const float4* p1 = (const float4*)(g_P + ((size_t)b * LL + l1) * NPROJ);
        #pragma unroll
        for (int i = 0; i < 6; i++) { ((float4*)P0)[i] = p0[i]; ((float4*)P1)[i] = p1[i]; }
    }
    float ba = b_attn[0];
    bool v0 = l0 < len, v1 = l1 < len;

    for (int j = 0; j < NHOP; j++) {
        float t = sc0[j] + ba;
        #pragma unroll
        for (int i = 0; i < 5; i++)
            if (i < j) { int k = j - 1 - i; t += sq[i][k] + sbd[1 + k]; }

        float s0 = v0 ? tanhf(P0[0] + t) : -1e30f;
        float s1 = v1 ? tanhf(P1[0] + t) : -1e30f;

        float m = fmaxf(s0, s1);
        #pragma unroll
        for (int off = 16; off; off >>= 1) m = fmaxf(m, __shfl_xor_sync(0xffffffffu, m, off));
        if (lane == 0) sw[warp][0] = m;
        __syncthreads();
        if (tid == 0) {
            float mm = sw[0][0];
            for (int w = 1; w < 8; w++) mm = fmaxf(mm, sw[w][0]);
            sbcast[0] = mm;
        }
        __syncthreads();
        float M = sbcast[0];

        float e0 = v0 ? expf(s0 - M) : 0.f;
        float e1 = v1 ? expf(s1 - M) : 0.f;
        float zs = e0 + e1;
        #pragma unroll
        for (int off = 16; off; off >>= 1) zs += __shfl_xor_sync(0xffffffffu, zs, off);
        if (lane == 0) sw[warp][1] = zs;
        __syncthreads();
        if (tid == 0) {
            float Z = 0.f;
            for (int w = 0; w < 8; w++) Z += sw[w][1];
            sbcast[1] = 1.f / Z;
        }
        __syncthreads();
        float rz = sbcast[1];
        float a0 = e0 * rz, a1 = e1 * rz;

        float wp[23];
        #pragma unroll
        for (int r = 0; r < 23; r++) wp[r] = a0 * P0[1 + r] + a1 * P1[1 + r];
        #pragma unroll
        for (int off = 16; off; off >>= 1)
            #pragma unroll
            for (int r = 0; r < 23; r++)
                wp[r] += __shfl_xor_sync(0xffffffffu, wp[r], off);
        if (lane == 0) {
            #pragma unroll
            for (int r = 0; r < 23; r++) sw[warp][r] = wp[r];
        }
        __syncthreads();
        if (tid < 23) {
            float s = 0.f;
            #pragma unroll
            for (int w = 0; w < 8; w++) s += sw[w][tid];
            sq[j][tid] = s;
        }
        __syncthreads();
    }

    if (tid < CC) {
        int c = tid;
        float lg = sc0[6 + c] + b_out[c];
        #pragma unroll
        for (int j = 0; j < NHOP; j++) {
            int k = 5 - j;
            lg += sq[j][5 + c * 6 + k] + sbd[6 + c * 6 + k];
        }
        out[b * CC + c] = lg;
    }
}

// ---------------------------------------------------------------------------
extern "C" void kernel_launch(void* const* d_in, const int* in_sizes, int n_in,
                              void* d_out, int out_size) {
    const int*   ctx_ids = (const int*)  d_in[0];
    const int*   tgt_ids = (const int*)  d_in[1];
    const int*   ctx_len = (const int*)  d_in[2];
    const int*   tgt_len = (const int*)  d_in[3];
    const int*   tgt_off = (const int*)  d_in[4];
    const float* E       = (const float*)d_in[5];
    const float* W_lin   = (const float*)d_in[6];
    const float* b_lin   = (const float*)d_in[7];
    const float* w_attn  = (const float*)d_in[8];
    const float* b_attn  = (const float*)d_in[9];
    const float* W_out   = (const float*)d_in[10];
    const float* b_out   = (const float*)d_in[11];
    float* out = (float*)d_out;

    const int heavySmem = NPROJ * DD * (int)sizeof(float)
                        + 4 * 32 * E_SLOT_ROW * (int)sizeof(float);
    cudaFuncSetAttribute(k_heavy, cudaFuncAttributeMaxDynamicSharedMemorySize,
                         heavySmem);

    k_chain_all<<<CHAIN_CTAS, 256>>>(W_lin, w_attn, W_out);
    k_heavy<<<HEAVY_CTAS, 256, heavySmem>>>(ctx_ids, E, ctx_len, tgt_off);
    k_solve<<<BB, 256>>>(tgt_ids, ctx_len, tgt_len, E, b_attn, b_lin, b_out, out);
}